// round 12
// baseline (speedup 1.0000x reference)
#include <cuda_runtime.h>
#include <cuda_bf16.h>
#include <cstdint>

// ---------------------------------------------------------------------------
// Problem constants
// ---------------------------------------------------------------------------
static constexpr int NE    = 32;    // experts
static constexpr int NH    = 512;   // hidden
static constexpr int NI    = 1024;  // intermediate
static constexpr int NT    = 4096;  // tokens
static constexpr int NCAP  = 512;   // per-expert capacity
static constexpr int NFLAT = 8192;  // T*K

// ---------------------------------------------------------------------------
// Device scratch (allocation-free: __device__ globals)
// ---------------------------------------------------------------------------
__device__ int   g_cnt[NE];
__device__ int   g_rows[NE * NCAP];
__device__ float g_act[(long long)NE * NCAP * NI];   // 64 MB activation buffer

// ---------------------------------------------------------------------------
// SMEM layout: 4 tiles of 128 rows x 64 bf16 (128 B/row) = 16 KB each
// ---------------------------------------------------------------------------
static constexpr int OFF_AHI = 0;
static constexpr int OFF_ALO = 16384;
static constexpr int OFF_BHI = 32768;
static constexpr int OFF_BLO = 49152;
static constexpr int SMEM_BYTES = 65536;

// ---------------------------------------------------------------------------
// PTX helpers (compute_103-legal: mma.sync + ldmatrix, NO tcgen05)
// ---------------------------------------------------------------------------
__device__ __forceinline__ uint32_t smem_u32(const void* p) {
    uint32_t a;
    asm("{ .reg .u64 t; cvta.to.shared.u64 t, %1; cvt.u32.u64 %0, t; }"
        : "=r"(a) : "l"(p));
    return a;
}

__device__ __forceinline__ void ldsm4(uint32_t& r0, uint32_t& r1,
                                      uint32_t& r2, uint32_t& r3, uint32_t a) {
    asm volatile("ldmatrix.sync.aligned.m8n8.x4.shared.b16 {%0,%1,%2,%3}, [%4];"
                 : "=r"(r0), "=r"(r1), "=r"(r2), "=r"(r3) : "r"(a));
}

__device__ __forceinline__ void mma16816(float* d, const uint32_t* a,
                                         const uint32_t* b) {
    asm volatile(
        "mma.sync.aligned.m16n8k16.row.col.f32.bf16.bf16.f32 "
        "{%0,%1,%2,%3}, {%4,%5,%6,%7}, {%8,%9}, {%0,%1,%2,%3};"
        : "+f"(d[0]), "+f"(d[1]), "+f"(d[2]), "+f"(d[3])
        : "r"(a[0]), "r"(a[1]), "r"(a[2]), "r"(a[3]), "r"(b[0]), "r"(b[1]));
}

// fp32 -> (bf16 hi, bf16 lo) split, stored swizzled (16B-unit xor within 128B row)
__device__ __forceinline__ void store_split(uint32_t hi_t, uint32_t lo_t,
                                            int row, int jj, float4 v) {
    uint32_t off = (uint32_t)(row * 128 + jj * 8);
    uint32_t sw  = off ^ ((off >> 3) & 0x70);
    __nv_bfloat16 h0 = __float2bfloat16(v.x);
    __nv_bfloat16 h1 = __float2bfloat16(v.y);
    __nv_bfloat16 h2 = __float2bfloat16(v.z);
    __nv_bfloat16 h3 = __float2bfloat16(v.w);
    __nv_bfloat16 l0 = __float2bfloat16(v.x - __bfloat162float(h0));
    __nv_bfloat16 l1 = __float2bfloat16(v.y - __bfloat162float(h1));
    __nv_bfloat16 l2 = __float2bfloat16(v.z - __bfloat162float(h2));
    __nv_bfloat16 l3 = __float2bfloat16(v.w - __bfloat162float(h3));
    uint32_t hA = (uint32_t)__bfloat16_as_ushort(h0) | ((uint32_t)__bfloat16_as_ushort(h1) << 16);
    uint32_t hB = (uint32_t)__bfloat16_as_ushort(h2) | ((uint32_t)__bfloat16_as_ushort(h3) << 16);
    uint32_t lA = (uint32_t)__bfloat16_as_ushort(l0) | ((uint32_t)__bfloat16_as_ushort(l1) << 16);
    uint32_t lB = (uint32_t)__bfloat16_as_ushort(l2) | ((uint32_t)__bfloat16_as_ushort(l3) << 16);
    asm volatile("st.shared.v2.b32 [%0], {%1, %2};" :: "r"(hi_t + sw), "r"(hA), "r"(hB) : "memory");
    asm volatile("st.shared.v2.b32 [%0], {%1, %2};" :: "r"(lo_t + sw), "r"(lA), "r"(lB) : "memory");
}

__device__ __forceinline__ float silu(float g) {
    return g / (1.0f + __expf(-g));
}

// Consume one staged K=64 chunk: 4 k-steps, split-bf16 (hh + hl + lh) MMAs.
// Warp (wm, wn) owns a 64x32 subtile of the 128x128 CTA tile.
__device__ __forceinline__ void mma_chunk(uint32_t sb, int lane, int wm, int wn,
                                          float acc[4][4][4]) {
    int a_row = wm * 64 + (lane & 7) + ((lane >> 3) & 1) * 8;
    int a_kh  = (lane >> 4) & 1;
    int b_row = wn * 32 + (lane & 7) + ((lane >> 4) & 1) * 8;
    int b_kh  = (lane >> 3) & 1;
#pragma unroll
    for (int ks = 0; ks < 4; ks++) {
        uint32_t bh[8], bl[8];
#pragma unroll
        for (int nb = 0; nb < 2; nb++) {
            uint32_t off = (uint32_t)((b_row + nb * 16) * 128 + (ks * 16 + b_kh * 8) * 2);
            uint32_t sw  = off ^ ((off >> 3) & 0x70);
            ldsm4(bh[nb*4+0], bh[nb*4+1], bh[nb*4+2], bh[nb*4+3], sb + OFF_BHI + sw);
            ldsm4(bl[nb*4+0], bl[nb*4+1], bl[nb*4+2], bl[nb*4+3], sb + OFF_BLO + sw);
        }
#pragma unroll
        for (int mi = 0; mi < 4; mi++) {
            uint32_t off = (uint32_t)((a_row + mi * 16) * 128 + (ks * 16 + a_kh * 8) * 2);
            uint32_t sw  = off ^ ((off >> 3) & 0x70);
            uint32_t ah[4], al[4];
            ldsm4(ah[0], ah[1], ah[2], ah[3], sb + OFF_AHI + sw);
            ldsm4(al[0], al[1], al[2], al[3], sb + OFF_ALO + sw);
#pragma unroll
            for (int ni = 0; ni < 4; ni++) {
                const uint32_t* bph = &bh[(ni >> 1) * 4 + (ni & 1) * 2];
                const uint32_t* bpl = &bl[(ni >> 1) * 4 + (ni & 1) * 2];
                mma16816(acc[mi][ni], ah, bph);
                mma16816(acc[mi][ni], ah, bpl);
                mma16816(acc[mi][ni], al, bph);
            }
        }
    }
}

// ---------------------------------------------------------------------------
// Kernel 0: zero output
// ---------------------------------------------------------------------------
__global__ void k_zero(float* __restrict__ out) {
    out[(size_t)blockIdx.x * blockDim.x + threadIdx.x] = 0.0f;
}

// ---------------------------------------------------------------------------
// Kernel 1: routing — per-expert block, ballot prefix-scan over flat slots.
// Matches the reference's cumsum-based Switch dispatch (pos >= CAP dropped).
//
// Index dtype detection: the reference declares int64, but JAX with default
// x64-disabled materializes int32. If the buffer really is int64 (little-
// endian), every odd 32-bit word is 0 (values < 32); if int32, the odd words
// are themselves uniform indices in [0,32) and are virtually never all zero.
// Scan the first NFLAT int32 words (always in-bounds) to pick the stride.
// ---------------------------------------------------------------------------
__global__ void k_route(const int* __restrict__ idx32) {
    int e   = blockIdx.x;
    int tid = threadIdx.x;
    int w   = tid >> 5;
    int l   = tid & 31;

    // dtype detection (identical result in every block)
    int nz = 0;
    for (int i = tid; i < NFLAT / 2; i += 256) nz |= idx32[2 * i + 1];
    int is32 = __syncthreads_or(nz);
    int stride = is32 ? 1 : 2;

    __shared__ int warp_tot[8];
    int base = 0;
    for (int it = 0; it < NFLAT / 256; it++) {
        int i  = it * 256 + tid;
        int ei = idx32[i * stride];
        bool flag = (ei == e);
        unsigned m = __ballot_sync(0xffffffffu, flag);
        int wpre = __popc(m & ((1u << l) - 1u));
        if (l == 0) warp_tot[w] = __popc(m);
        __syncthreads();
        int wbase = 0;
#pragma unroll
        for (int j = 0; j < 8; j++) if (j < w) wbase += warp_tot[j];
        int tot = 0;
#pragma unroll
        for (int j = 0; j < 8; j++) tot += warp_tot[j];
        int pos = base + wbase + wpre;
        if (flag && pos < NCAP) g_rows[e * NCAP + pos] = i;
        base += tot;
        __syncthreads();
    }
    if (tid == 0) g_cnt[e] = (base > NCAP) ? NCAP : base;
}

// ---------------------------------------------------------------------------
// Kernel 2: GEMM1 + SwiGLU.  Per CTA: expert e, m-tile (128 rows), n-pair p.
// D[128 x 128] = X[128 x 512] * W^T.  B rows interleave gate/up (even=gate,
// odd=up) so each thread holds (gate_c, up_c) in adjacent accumulator regs.
// ---------------------------------------------------------------------------
__global__ __launch_bounds__(256, 2)
void k_gemm1(const float* __restrict__ hidden, const float* __restrict__ gup) {
    int b   = blockIdx.x;
    int e   = b >> 6;
    int rem = b & 63;
    int mt  = rem >> 4;
    int p   = rem & 15;
    int cnt = g_cnt[e];
    int row0 = mt * 128;
    if (row0 >= cnt) return;

    extern __shared__ char smem[];
    uint32_t sb = smem_u32(smem);
    int tid = threadIdx.x, lane = tid & 31, wid = tid >> 5;
    int wm = wid & 1, wn = wid >> 1;
    int srow = tid >> 4;   // 0..15
    int jj   = tid & 15;   // float4 index within K=64 chunk

    float acc[4][4][4];
#pragma unroll
    for (int mi = 0; mi < 4; mi++)
#pragma unroll
        for (int ni = 0; ni < 4; ni++)
#pragma unroll
            for (int q = 0; q < 4; q++) acc[mi][ni][q] = 0.0f;

#pragma unroll 1
    for (int chunk = 0; chunk < 8; chunk++) {
        int k0 = chunk * 64;
#pragma unroll
        for (int pass = 0; pass < 8; pass++) {
            int row = pass * 16 + srow;
            // A: gathered tokens (zero-pad rows beyond cnt)
            float4 v = make_float4(0.f, 0.f, 0.f, 0.f);
            int mr = row0 + row;
            if (mr < cnt) {
                int f = g_rows[e * NCAP + mr];
                v = *(const float4*)(hidden + (size_t)(f >> 1) * NH + k0 + jj * 4);
            }
            store_split(sb + OFF_AHI, sb + OFF_ALO, row, jj, v);
            // B: interleaved gate/up rows
            int gr = ((row & 1) == 0) ? (p * 64 + (row >> 1))
                                      : (NI + p * 64 + (row >> 1));
            float4 wv = *(const float4*)(gup + ((size_t)e * 2 * NI + gr) * NH + k0 + jj * 4);
            store_split(sb + OFF_BHI, sb + OFF_BLO, row, jj, wv);
        }
        __syncthreads();
        mma_chunk(sb, lane, wm, wn, acc);
        __syncthreads();
    }

    // Epilogue: act[m, p*64 + c] = silu(gate_c) * up_c
    int g = lane >> 2, q = lane & 3;
#pragma unroll
    for (int mi = 0; mi < 4; mi++) {
        int m0 = row0 + wm * 64 + mi * 16 + g;
        float* base0 = g_act + ((size_t)e * NCAP + m0) * NI;
        float* base8 = base0 + (size_t)8 * NI;
#pragma unroll
        for (int ni = 0; ni < 4; ni++) {
            int c = p * 64 + wn * 16 + ni * 4 + q;
            base0[c] = silu(acc[mi][ni][0]) * acc[mi][ni][1];
            base8[c] = silu(acc[mi][ni][2]) * acc[mi][ni][3];
        }
    }
}

// ---------------------------------------------------------------------------
// Kernel 3: GEMM2 + weighted scatter.  Per CTA: expert e, m-tile, h-tile(128).
// Y[128 x 128] = act[128 x 1024] * down^T; out[t, h0+j] += w * y (atomic).
// ---------------------------------------------------------------------------
__global__ __launch_bounds__(256, 2)
void k_gemm2(const float* __restrict__ down, const float* __restrict__ wts,
             float* __restrict__ out) {
    int b   = blockIdx.x;
    int e   = b >> 4;
    int rem = b & 15;
    int mt  = rem >> 2;
    int ht  = rem & 3;
    int cnt = g_cnt[e];
    int row0 = mt * 128;
    if (row0 >= cnt) return;
    int h0 = ht * 128;

    extern __shared__ char smem[];
    uint32_t sb = smem_u32(smem);
    int tid = threadIdx.x, lane = tid & 31, wid = tid >> 5;
    int wm = wid & 1, wn = wid >> 1;
    int srow = tid >> 4;
    int jj   = tid & 15;

    float acc[4][4][4];
#pragma unroll
    for (int mi = 0; mi < 4; mi++)
#pragma unroll
        for (int ni = 0; ni < 4; ni++)
#pragma unroll
            for (int q = 0; q < 4; q++) acc[mi][ni][q] = 0.0f;

#pragma unroll 1
    for (int chunk = 0; chunk < 16; chunk++) {
        int k0 = chunk * 64;
#pragma unroll
        for (int pass = 0; pass < 8; pass++) {
            int row = pass * 16 + srow;
            float4 v = *(const float4*)(g_act + ((size_t)e * NCAP + row0 + row) * NI + k0 + jj * 4);
            store_split(sb + OFF_AHI, sb + OFF_ALO, row, jj, v);
            float4 wv = *(const float4*)(down + ((size_t)e * NH + h0 + row) * NI + k0 + jj * 4);
            store_split(sb + OFF_BHI, sb + OFF_BLO, row, jj, wv);
        }
        __syncthreads();
        mma_chunk(sb, lane, wm, wn, acc);
        __syncthreads();
    }

    // Epilogue: weighted atomic scatter to out[token]
    int g = lane >> 2, q = lane & 3;
#pragma unroll
    for (int mi = 0; mi < 4; mi++) {
        int m0 = row0 + wm * 64 + mi * 16 + g;
#pragma unroll
        for (int half = 0; half < 2; half++) {
            int m = m0 + half * 8;
            if (m < cnt) {
                int f   = g_rows[e * NCAP + m];
                float w = wts[f];
                float* op = out + (size_t)(f >> 1) * NH + h0;
#pragma unroll
                for (int ni = 0; ni < 4; ni++) {
                    int j = wn * 32 + ni * 8 + q * 2;
                    atomicAdd(op + j,     w * acc[mi][ni][half * 2 + 0]);
                    atomicAdd(op + j + 1, w * acc[mi][ni][half * 2 + 1]);
                }
            }
        }
    }
}

// ---------------------------------------------------------------------------
// Launch
// ---------------------------------------------------------------------------
extern "C" void kernel_launch(void* const* d_in, const int* in_sizes, int n_in,
                              void* d_out, int out_size) {
    (void)in_sizes; (void)n_in; (void)out_size;
    const float* hidden = (const float*)d_in[0];
    const int*   idx32  = (const int*)d_in[1];     // int32 OR int64 (auto-detected)
    const float* wts    = (const float*)d_in[2];
    const float* gup    = (const float*)d_in[3];
    const float* down   = (const float*)d_in[4];
    float*       out    = (float*)d_out;

    cudaFuncSetAttribute(k_gemm1, cudaFuncAttributeMaxDynamicSharedMemorySize, SMEM_BYTES);
    cudaFuncSetAttribute(k_gemm2, cudaFuncAttributeMaxDynamicSharedMemorySize, SMEM_BYTES);

    k_zero<<<(NT * NH) / 256, 256>>>(out);
    k_route<<<NE, 256>>>(idx32);
    k_gemm1<<<NE * 4 * 16, 256, SMEM_BYTES>>>(hidden, gup);
    k_gemm2<<<NE * 4 * 4, 256, SMEM_BYTES>>>(down, wts, out);
}

// round 14
// speedup vs baseline: 1.1869x; 1.1869x over previous
#include <cuda_runtime.h>
#include <cuda_bf16.h>
#include <cstdint>

// ---------------------------------------------------------------------------
// Problem constants
// ---------------------------------------------------------------------------
static constexpr int NE    = 32;    // experts
static constexpr int NH    = 512;   // hidden
static constexpr int NI    = 1024;  // intermediate
static constexpr int NT    = 4096;  // tokens
static constexpr int NCAP  = 512;   // per-expert capacity
static constexpr int NFLAT = 8192;  // T*K

// ---------------------------------------------------------------------------
// Device scratch (allocation-free: __device__ globals)
// ---------------------------------------------------------------------------
__device__ int   g_cnt[NE];
__device__ int   g_rows[NE * NCAP];
__device__ float g_act[(long long)NE * NCAP * NI];   // 64 MB activation buffer

// ---------------------------------------------------------------------------
// SMEM: two pipeline stages; each stage = 4 tiles of 128 rows x 32 bf16
// (64 B/row) = 8 KB per tile, 32 KB per stage, 64 KB total.
// ---------------------------------------------------------------------------
static constexpr int T_AHI = 0;
static constexpr int T_ALO = 8192;
static constexpr int T_BHI = 16384;
static constexpr int T_BLO = 24576;
static constexpr int STAGE_BYTES = 32768;
static constexpr int SMEM_BYTES  = 65536;

// ---------------------------------------------------------------------------
// PTX helpers (compute_103-legal: mma.sync + ldmatrix, NO tcgen05)
// ---------------------------------------------------------------------------
__device__ __forceinline__ uint32_t smem_u32(const void* p) {
    uint32_t a;
    asm("{ .reg .u64 t; cvta.to.shared.u64 t, %1; cvt.u32.u64 %0, t; }"
        : "=r"(a) : "l"(p));
    return a;
}

__device__ __forceinline__ void ldsm4(uint32_t& r0, uint32_t& r1,
                                      uint32_t& r2, uint32_t& r3, uint32_t a) {
    asm volatile("ldmatrix.sync.aligned.m8n8.x4.shared.b16 {%0,%1,%2,%3}, [%4];"
                 : "=r"(r0), "=r"(r1), "=r"(r2), "=r"(r3) : "r"(a));
}

__device__ __forceinline__ void mma16816(float* d, const uint32_t* a,
                                         const uint32_t* b) {
    asm volatile(
        "mma.sync.aligned.m16n8k16.row.col.f32.bf16.bf16.f32 "
        "{%0,%1,%2,%3}, {%4,%5,%6,%7}, {%8,%9}, {%0,%1,%2,%3};"
        : "+f"(d[0]), "+f"(d[1]), "+f"(d[2]), "+f"(d[3])
        : "r"(a[0]), "r"(a[1]), "r"(a[2]), "r"(a[3]), "r"(b[0]), "r"(b[1]));
}

// 64B-row swizzle: xor 16B-chunk index (bits[4:5]) with row bits (off bits[7:8]).
// For any 8-row-aligned ldmatrix read (fixed chunk), the 8 addresses land on
// 8 distinct 16B slots of the 128B bank cycle -> conflict-free.
__device__ __forceinline__ uint32_t swz64(uint32_t off) {
    return off ^ ((off >> 3) & 0x30);
}

// fp32x4 -> (bf16 hi, bf16 lo) split, stored swizzled into hi/lo tiles
__device__ __forceinline__ void store_split(uint32_t hi_t, uint32_t lo_t,
                                            int row, int jj, float4 v) {
    uint32_t sw = swz64((uint32_t)(row * 64 + jj * 8));
    __nv_bfloat16 h0 = __float2bfloat16(v.x);
    __nv_bfloat16 h1 = __float2bfloat16(v.y);
    __nv_bfloat16 h2 = __float2bfloat16(v.z);
    __nv_bfloat16 h3 = __float2bfloat16(v.w);
    __nv_bfloat16 l0 = __float2bfloat16(v.x - __bfloat162float(h0));
    __nv_bfloat16 l1 = __float2bfloat16(v.y - __bfloat162float(h1));
    __nv_bfloat16 l2 = __float2bfloat16(v.z - __bfloat162float(h2));
    __nv_bfloat16 l3 = __float2bfloat16(v.w - __bfloat162float(h3));
    uint32_t hA = (uint32_t)__bfloat16_as_ushort(h0) | ((uint32_t)__bfloat16_as_ushort(h1) << 16);
    uint32_t hB = (uint32_t)__bfloat16_as_ushort(h2) | ((uint32_t)__bfloat16_as_ushort(h3) << 16);
    uint32_t lA = (uint32_t)__bfloat16_as_ushort(l0) | ((uint32_t)__bfloat16_as_ushort(l1) << 16);
    uint32_t lB = (uint32_t)__bfloat16_as_ushort(l2) | ((uint32_t)__bfloat16_as_ushort(l3) << 16);
    asm volatile("st.shared.v2.b32 [%0], {%1, %2};" :: "r"(hi_t + sw), "r"(hA), "r"(hB) : "memory");
    asm volatile("st.shared.v2.b32 [%0], {%1, %2};" :: "r"(lo_t + sw), "r"(lA), "r"(lB) : "memory");
}

__device__ __forceinline__ float silu(float g) {
    return g / (1.0f + __expf(-g));
}

// Consume one staged K=32 chunk: 2 k-steps, split-bf16 (hh + hl + lh) MMAs.
// Warp (wm, wn) owns a 64x32 subtile of the 128x128 CTA tile.
__device__ __forceinline__ void mma_chunk(uint32_t st, int lane, int wm, int wn,
                                          float acc[4][4][4]) {
    int a_row = wm * 64 + (lane & 7) + ((lane >> 3) & 1) * 8;
    int a_kh  = (lane >> 4) & 1;
    int b_row = wn * 32 + (lane & 7) + ((lane >> 4) & 1) * 8;
    int b_kh  = (lane >> 3) & 1;
#pragma unroll
    for (int ks = 0; ks < 2; ks++) {
        uint32_t bh[8], bl[8];
#pragma unroll
        for (int nb = 0; nb < 2; nb++) {
            uint32_t sw = swz64((uint32_t)((b_row + nb * 16) * 64 + (ks * 16 + b_kh * 8) * 2));
            ldsm4(bh[nb*4+0], bh[nb*4+1], bh[nb*4+2], bh[nb*4+3], st + T_BHI + sw);
            ldsm4(bl[nb*4+0], bl[nb*4+1], bl[nb*4+2], bl[nb*4+3], st + T_BLO + sw);
        }
#pragma unroll
        for (int mi = 0; mi < 4; mi++) {
            uint32_t sw = swz64((uint32_t)((a_row + mi * 16) * 64 + (ks * 16 + a_kh * 8) * 2));
            uint32_t ah[4], al[4];
            ldsm4(ah[0], ah[1], ah[2], ah[3], st + T_AHI + sw);
            ldsm4(al[0], al[1], al[2], al[3], st + T_ALO + sw);
#pragma unroll
            for (int ni = 0; ni < 4; ni++) {
                const uint32_t* bph = &bh[(ni >> 1) * 4 + (ni & 1) * 2];
                const uint32_t* bpl = &bl[(ni >> 1) * 4 + (ni & 1) * 2];
                mma16816(acc[mi][ni], ah, bph);
                mma16816(acc[mi][ni], ah, bpl);
                mma16816(acc[mi][ni], al, bph);
            }
        }
    }
}

// ---------------------------------------------------------------------------
// Kernel 0: zero output
// ---------------------------------------------------------------------------
__global__ void k_zero(float* __restrict__ out) {
    out[(size_t)blockIdx.x * blockDim.x + threadIdx.x] = 0.0f;
}

// ---------------------------------------------------------------------------
// Kernel 1: routing — per-expert block, ballot prefix-scan over flat slots.
// Matches the reference's cumsum-based Switch dispatch (pos >= CAP dropped).
// Index dtype auto-detected (JAX x64-disabled materializes int32).
// ---------------------------------------------------------------------------
__global__ void k_route(const int* __restrict__ idx32) {
    int e   = blockIdx.x;
    int tid = threadIdx.x;
    int w   = tid >> 5;
    int l   = tid & 31;

    int nz = 0;
    for (int i = tid; i < NFLAT / 2; i += 256) nz |= idx32[2 * i + 1];
    int is32 = __syncthreads_or(nz);
    int stride = is32 ? 1 : 2;

    __shared__ int warp_tot[8];
    int base = 0;
    for (int it = 0; it < NFLAT / 256; it++) {
        int i  = it * 256 + tid;
        int ei = idx32[i * stride];
        bool flag = (ei == e);
        unsigned m = __ballot_sync(0xffffffffu, flag);
        int wpre = __popc(m & ((1u << l) - 1u));
        if (l == 0) warp_tot[w] = __popc(m);
        __syncthreads();
        int wbase = 0;
#pragma unroll
        for (int j = 0; j < 8; j++) if (j < w) wbase += warp_tot[j];
        int tot = 0;
#pragma unroll
        for (int j = 0; j < 8; j++) tot += warp_tot[j];
        int pos = base + wbase + wpre;
        if (flag && pos < NCAP) g_rows[e * NCAP + pos] = i;
        base += tot;
        __syncthreads();
    }
    if (tid == 0) g_cnt[e] = (base > NCAP) ? NCAP : base;
}

// ---------------------------------------------------------------------------
// Kernel 2: GEMM1 + SwiGLU.  Per CTA: expert e, m-tile (128 rows), n-pair p.
// D[128 x 128] = X[128 x 512] * W^T.  B rows interleave gate/up (even=gate,
// odd=up).  Double-buffered: prefetch chunk c+1 (LDG to regs) before the
// MMAs of chunk c; one __syncthreads per chunk.
// ---------------------------------------------------------------------------
__global__ __launch_bounds__(256, 2)
void k_gemm1(const float* __restrict__ hidden, const float* __restrict__ gup) {
    int b   = blockIdx.x;
    int e   = b >> 6;
    int rem = b & 63;
    int mt  = rem >> 4;
    int p   = rem & 15;
    int cnt = g_cnt[e];
    int row0 = mt * 128;
    if (row0 >= cnt) return;

    extern __shared__ char smem[];
    uint32_t sb = smem_u32(smem);
    int tid = threadIdx.x, lane = tid & 31, wid = tid >> 5;
    int wm = wid & 1, wn = wid >> 1;
    int srow = tid >> 3;   // 0..31 (row within 32-row pass)
    int jj   = tid & 7;    // float4 index within K=32 chunk

    // Hoisted per-pass row pointers (4 passes of 32 rows)
    const float* aptr[4];
    const float* bptr[4];
#pragma unroll
    for (int ps = 0; ps < 4; ps++) {
        int row = ps * 32 + srow;
        int mr  = row0 + row;
        if (mr < cnt) {
            int f = g_rows[e * NCAP + mr];
            aptr[ps] = hidden + (size_t)(f >> 1) * NH;
        } else {
            aptr[ps] = nullptr;
        }
        int gr = ((row & 1) == 0) ? (p * 64 + (row >> 1))
                                  : (NI + p * 64 + (row >> 1));
        bptr[ps] = gup + ((size_t)e * 2 * NI + gr) * NH;
    }

    float acc[4][4][4];
#pragma unroll
    for (int mi = 0; mi < 4; mi++)
#pragma unroll
        for (int ni = 0; ni < 4; ni++)
#pragma unroll
            for (int q = 0; q < 4; q++) acc[mi][ni][q] = 0.0f;

    float4 ra[4], rb[4];
    // preload chunk 0
#pragma unroll
    for (int ps = 0; ps < 4; ps++) {
        ra[ps] = aptr[ps] ? *(const float4*)(aptr[ps] + jj * 4)
                          : make_float4(0.f, 0.f, 0.f, 0.f);
        rb[ps] = *(const float4*)(bptr[ps] + jj * 4);
    }
#pragma unroll
    for (int ps = 0; ps < 4; ps++) {
        store_split(sb + T_AHI, sb + T_ALO, ps * 32 + srow, jj, ra[ps]);
        store_split(sb + T_BHI, sb + T_BLO, ps * 32 + srow, jj, rb[ps]);
    }
    __syncthreads();

    constexpr int NC = NH / 32;  // 16 chunks
#pragma unroll 1
    for (int c = 0; c < NC; c++) {
        if (c + 1 < NC) {
            int k0 = (c + 1) * 32;
#pragma unroll
            for (int ps = 0; ps < 4; ps++) {
                ra[ps] = aptr[ps] ? *(const float4*)(aptr[ps] + k0 + jj * 4)
                                  : make_float4(0.f, 0.f, 0.f, 0.f);
                rb[ps] = *(const float4*)(bptr[ps] + k0 + jj * 4);
            }
        }
        mma_chunk(sb + (c & 1) * STAGE_BYTES, lane, wm, wn, acc);
        if (c + 1 < NC) {
            uint32_t st = sb + ((c + 1) & 1) * STAGE_BYTES;
#pragma unroll
            for (int ps = 0; ps < 4; ps++) {
                store_split(st + T_AHI, st + T_ALO, ps * 32 + srow, jj, ra[ps]);
                store_split(st + T_BHI, st + T_BLO, ps * 32 + srow, jj, rb[ps]);
            }
        }
        __syncthreads();
    }

    // Epilogue: act[m, p*64 + c] = silu(gate_c) * up_c
    int g = lane >> 2, q = lane & 3;
#pragma unroll
    for (int mi = 0; mi < 4; mi++) {
        int m0 = row0 + wm * 64 + mi * 16 + g;
        float* base0 = g_act + ((size_t)e * NCAP + m0) * NI;
        float* base8 = base0 + (size_t)8 * NI;
#pragma unroll
        for (int ni = 0; ni < 4; ni++) {
            int cc = p * 64 + wn * 16 + ni * 4 + q;
            base0[cc] = silu(acc[mi][ni][0]) * acc[mi][ni][1];
            base8[cc] = silu(acc[mi][ni][2]) * acc[mi][ni][3];
        }
    }
}

// ---------------------------------------------------------------------------
// Kernel 3: GEMM2 + weighted scatter.  Per CTA: expert e, m-tile, h-tile(128).
// Y[128 x 128] = act[128 x 1024] * down^T; out[t, h0+j] += w * y (atomic).
// Same double-buffered pipeline.
// ---------------------------------------------------------------------------
__global__ __launch_bounds__(256, 2)
void k_gemm2(const float* __restrict__ down, const float* __restrict__ wts,
             float* __restrict__ out) {
    int b   = blockIdx.x;
    int e   = b >> 4;
    int rem = b & 15;
    int mt  = rem >> 2;
    int ht  = rem & 3;
    int cnt = g_cnt[e];
    int row0 = mt * 128;
    if (row0 >= cnt) return;
    int h0 = ht * 128;

    extern __shared__ char smem[];
    uint32_t sb = smem_u32(smem);
    int tid = threadIdx.x, lane = tid & 31, wid = tid >> 5;
    int wm = wid & 1, wn = wid >> 1;
    int srow = tid >> 3;
    int jj   = tid & 7;

    const float* aptr[4];
    const float* bptr[4];
#pragma unroll
    for (int ps = 0; ps < 4; ps++) {
        int row = ps * 32 + srow;
        aptr[ps] = g_act + ((size_t)e * NCAP + row0 + row) * NI;
        bptr[ps] = down + ((size_t)e * NH + h0 + row) * NI;
    }

    float acc[4][4][4];
#pragma unroll
    for (int mi = 0; mi < 4; mi++)
#pragma unroll
        for (int ni = 0; ni < 4; ni++)
#pragma unroll
            for (int q = 0; q < 4; q++) acc[mi][ni][q] = 0.0f;

    float4 ra[4], rb[4];
#pragma unroll
    for (int ps = 0; ps < 4; ps++) {
        ra[ps] = *(const float4*)(aptr[ps] + jj * 4);
        rb[ps] = *(const float4*)(bptr[ps] + jj * 4);
    }
#pragma unroll
    for (int ps = 0; ps < 4; ps++) {
        store_split(sb + T_AHI, sb + T_ALO, ps * 32 + srow, jj, ra[ps]);
        store_split(sb + T_BHI, sb + T_BLO, ps * 32 + srow, jj, rb[ps]);
    }
    __syncthreads();

    constexpr int NC = NI / 32;  // 32 chunks
#pragma unroll 1
    for (int c = 0; c < NC; c++) {
        if (c + 1 < NC) {
            int k0 = (c + 1) * 32;
#pragma unroll
            for (int ps = 0; ps < 4; ps++) {
                ra[ps] = *(const float4*)(aptr[ps] + k0 + jj * 4);
                rb[ps] = *(const float4*)(bptr[ps] + k0 + jj * 4);
            }
        }
        mma_chunk(sb + (c & 1) * STAGE_BYTES, lane, wm, wn, acc);
        if (c + 1 < NC) {
            uint32_t st = sb + ((c + 1) & 1) * STAGE_BYTES;
#pragma unroll
            for (int ps = 0; ps < 4; ps++) {
                store_split(st + T_AHI, st + T_ALO, ps * 32 + srow, jj, ra[ps]);
                store_split(st + T_BHI, st + T_BLO, ps * 32 + srow, jj, rb[ps]);
            }
        }
        __syncthreads();
    }

    // Epilogue: weighted atomic scatter to out[token]
    int g = lane >> 2, q = lane & 3;
#pragma unroll
    for (int mi = 0; mi < 4; mi++) {
        int m0 = row0 + wm * 64 + mi * 16 + g;
#pragma unroll
        for (int half = 0; half < 2; half++) {
            int m = m0 + half * 8;
            if (m < cnt) {
                int f   = g_rows[e * NCAP + m];
                float w = wts[f];
                float* op = out + (size_t)(f >> 1) * NH + h0;
#pragma unroll
                for (int ni = 0; ni < 4; ni++) {
                    int j = wn * 32 + ni * 8 + q * 2;
                    atomicAdd(op + j,     w * acc[mi][ni][half * 2 + 0]);
                    atomicAdd(op + j + 1, w * acc[mi][ni][half * 2 + 1]);
                }
            }
        }
    }
}

// ---------------------------------------------------------------------------
// Launch
// ---------------------------------------------------------------------------
extern "C" void kernel_launch(void* const* d_in, const int* in_sizes, int n_in,
                              void* d_out, int out_size) {
    (void)in_sizes; (void)n_in; (void)out_size;
    const float* hidden = (const float*)d_in[0];
    const int*   idx32  = (const int*)d_in[1];     // int32 OR int64 (auto-detected)
    const float* wts    = (const float*)d_in[2];
    const float* gup    = (const float*)d_in[3];
    const float* down   = (const float*)d_in[4];
    float*       out    = (float*)d_out;

    cudaFuncSetAttribute(k_gemm1, cudaFuncAttributeMaxDynamicSharedMemorySize, SMEM_BYTES);
    cudaFuncSetAttribute(k_gemm2, cudaFuncAttributeMaxDynamicSharedMemorySize, SMEM_BYTES);

    k_zero<<<(NT * NH) / 256, 256>>>(out);
    k_route<<<NE, 256>>>(idx32);
    k_gemm1<<<NE * 4 * 16, 256, SMEM_BYTES>>>(hidden, gup);
    k_gemm2<<<NE * 4 * 4, 256, SMEM_BYTES>>>(down, wts, out);
}